// round 4
// baseline (speedup 1.0000x reference)
#include <cuda_runtime.h>
#include <cstdint>

// Segment-mean over sorted segment ids, two-phase:
//   A) vectorized boundary scan builds seg_start[] offsets table
//   B) one WARP per molecule streams its rows (register-only reduce, no smem)
// atom_hiddens: [n_atoms, 128] f32 ; segment_ids: [n_atoms] i32 (sorted) ;
// out: [n_mols, 128] f32.

static constexpr int HIDDEN = 128;
static constexpr int MOLS_PER_CTA = 4;             // 4 warps = 4 molecules
static constexpr int MAX_MOLS = 4 * 1024 * 1024;   // scratch capacity (16 MB)

__device__ int g_seg_start[MAX_MOLS + 1];

// ---- Kernel A: find segment boundaries (int4-vectorized pass over ids) ----
__global__ __launch_bounds__(256)
void seg_offsets_kernel(const int* __restrict__ ids, int n_atoms, int n_mols) {
    const int base = (blockIdx.x * 256 + threadIdx.x) * 4;
    if (base >= n_atoms) return;

    if (base == 0) {
        g_seg_start[__ldg(ids)] = 0;       // first segment start
        g_seg_start[n_mols] = n_atoms;     // sentinel
    }

    if (base + 3 < n_atoms) {
        const int4 v = __ldg(reinterpret_cast<const int4*>(ids + base));
        const int prev = (base > 0) ? __ldg(ids + base - 1) : v.x;
        if (base > 0 && v.x != prev) g_seg_start[v.x] = base;
        if (v.y != v.x) g_seg_start[v.y] = base + 1;
        if (v.z != v.y) g_seg_start[v.z] = base + 2;
        if (v.w != v.z) g_seg_start[v.w] = base + 3;
    } else {
        for (int i = base; i < n_atoms; ++i) {
            if (i > 0 && __ldg(ids + i) != __ldg(ids + i - 1))
                g_seg_start[__ldg(ids + i)] = i;
        }
    }
}

// ---- Kernel B: one warp per molecule, register-resident reduce ----
__global__ __launch_bounds__(32 * MOLS_PER_CTA, 16)
void seg_mean_kernel(const float* __restrict__ x,
                     float*       __restrict__ out,
                     int n_mols) {
    const int warp = threadIdx.x >> 5;
    const int lane = threadIdx.x & 31;
    const int mol  = blockIdx.x * MOLS_PER_CTA + warp;
    if (mol >= n_mols) return;

    // Broadcast loads; adjacent warps/CTAs share cache lines.
    const int start = __ldg(&g_seg_start[mol]);
    const int end   = __ldg(&g_seg_start[mol + 1]);
    const int count = end - start;

    // Lane covers columns 4*lane..4*lane+3; iterate over all rows.
    // Unrolled x4 for MLP (4 independent LDG.128 in flight per thread).
    const float4* __restrict__ xv =
        reinterpret_cast<const float4*>(x) + lane;       // element stride = 32 float4s/row

    float4 a0 = make_float4(0.f, 0.f, 0.f, 0.f);
    float4 a1 = make_float4(0.f, 0.f, 0.f, 0.f);
    float4 a2 = make_float4(0.f, 0.f, 0.f, 0.f);
    float4 a3 = make_float4(0.f, 0.f, 0.f, 0.f);

    int r = start;
    for (; r + 3 < end; r += 4) {
        const float4 v0 = __ldg(xv + (size_t)(r + 0) * 32);
        const float4 v1 = __ldg(xv + (size_t)(r + 1) * 32);
        const float4 v2 = __ldg(xv + (size_t)(r + 2) * 32);
        const float4 v3 = __ldg(xv + (size_t)(r + 3) * 32);
        a0.x += v0.x; a0.y += v0.y; a0.z += v0.z; a0.w += v0.w;
        a1.x += v1.x; a1.y += v1.y; a1.z += v1.z; a1.w += v1.w;
        a2.x += v2.x; a2.y += v2.y; a2.z += v2.z; a2.w += v2.w;
        a3.x += v3.x; a3.y += v3.y; a3.z += v3.z; a3.w += v3.w;
    }
    for (; r < end; ++r) {
        const float4 v = __ldg(xv + (size_t)r * 32);
        a0.x += v.x; a0.y += v.y; a0.z += v.z; a0.w += v.w;
    }

    const float inv = (count > 0) ? (1.0f / (float)count) : 0.0f;
    float4 s;
    s.x = (a0.x + a1.x + a2.x + a3.x) * inv;
    s.y = (a0.y + a1.y + a2.y + a3.y) * inv;
    s.z = (a0.z + a1.z + a2.z + a3.z) * inv;
    s.w = (a0.w + a1.w + a2.w + a3.w) * inv;

    reinterpret_cast<float4*>(out + (size_t)mol * HIDDEN)[lane] = s;
}

extern "C" void kernel_launch(void* const* d_in, const int* in_sizes, int n_in,
                              void* d_out, int out_size) {
    const float* atom_hiddens = (const float*)d_in[0];
    const int*   segment_ids  = (const int*)d_in[1];
    float* out = (float*)d_out;

    const int n_atoms = in_sizes[1];          // segment_ids element count
    const int n_mols  = out_size / HIDDEN;    // output rows

    const int gridA = (n_atoms / 4 + 255) / 256 + 1;
    seg_offsets_kernel<<<gridA, 256>>>(segment_ids, n_atoms, n_mols);

    const int gridB = (n_mols + MOLS_PER_CTA - 1) / MOLS_PER_CTA;
    seg_mean_kernel<<<gridB, 32 * MOLS_PER_CTA>>>(atom_hiddens, out, n_mols);
}

// round 5
// speedup vs baseline: 1.0771x; 1.0771x over previous
#include <cuda_runtime.h>
#include <cstdint>

// Segment-mean over sorted segment ids, two-phase:
//   A) int4-vectorized boundary scan builds seg_start[] offsets table
//   B) persistent-style: each CTA owns a contiguous chunk of molecules;
//      per molecule: 4 warps x 5 independent LDG.128, smem reduce, STG.128
// atom_hiddens: [n_atoms, 128] f32 ; segment_ids: [n_atoms] i32 (sorted) ;
// out: [n_mols, 128] f32.

static constexpr int HIDDEN = 128;
static constexpr int MAX_MOLS = 4 * 1024 * 1024;   // scratch capacity (16 MB)
static constexpr int GRID_B = 2432;                // ~16 CTAs/SM on 148-152 SMs

__device__ int g_seg_start[MAX_MOLS + 1];

// ---- Kernel A: find segment boundaries (int4-vectorized pass over ids) ----
__global__ __launch_bounds__(256)
void seg_offsets_kernel(const int* __restrict__ ids, int n_atoms, int n_mols) {
    const int base = (blockIdx.x * 256 + threadIdx.x) * 4;
    if (base >= n_atoms) return;

    if (base == 0) {
        g_seg_start[__ldg(ids)] = 0;       // first segment start
        g_seg_start[n_mols] = n_atoms;     // sentinel
    }

    if (base + 3 < n_atoms) {
        const int4 v = __ldg(reinterpret_cast<const int4*>(ids + base));
        if (base > 0 && v.x != __ldg(ids + base - 1)) g_seg_start[v.x] = base;
        if (v.y != v.x) g_seg_start[v.y] = base + 1;
        if (v.z != v.y) g_seg_start[v.z] = base + 2;
        if (v.w != v.z) g_seg_start[v.w] = base + 3;
    } else {
        for (int i = base; i < n_atoms; ++i) {
            if (i > 0 && __ldg(ids + i) != __ldg(ids + i - 1))
                g_seg_start[__ldg(ids + i)] = i;
        }
    }
}

// ---- Kernel B: contiguous-chunk persistent, block-per-molecule inner ----
__global__ __launch_bounds__(128, 16)
void seg_mean_kernel(const float* __restrict__ x,
                     float*       __restrict__ out,
                     int n_mols) {
    const int t    = threadIdx.x;
    const int warp = t >> 5;
    const int lane = t & 31;

    __shared__ alignas(16) float s_part[4][HIDDEN];

    // Contiguous molecule chunk per CTA: sequential offset loads (cache-hot)
    // and contiguous row data (DRAM-page friendly).
    const int chunk     = (n_mols + GRID_B - 1) / GRID_B;
    const int mol_begin = blockIdx.x * chunk;
    const int mol_end   = min(mol_begin + chunk, n_mols);

    const float4* __restrict__ xv = reinterpret_cast<const float4*>(x) + lane;

    for (int mol = mol_begin; mol < mol_end; ++mol) {
        const int start = __ldg(&g_seg_start[mol]);
        const int end   = __ldg(&g_seg_start[mol + 1]);
        const int count = end - start;

        // Warp w accumulates rows start+w, start+w+4, ...
        float4 acc = make_float4(0.f, 0.f, 0.f, 0.f);
        #pragma unroll 5
        for (int r = start + warp; r < end; r += 4) {
            const float4 v = __ldg(xv + (size_t)r * 32);
            acc.x += v.x; acc.y += v.y; acc.z += v.z; acc.w += v.w;
        }

        *reinterpret_cast<float4*>(&s_part[warp][lane * 4]) = acc;
        __syncthreads();

        const float sum = s_part[0][t] + s_part[1][t] + s_part[2][t] + s_part[3][t];
        const float inv = (count > 0) ? (1.0f / (float)count) : 0.0f;
        out[(size_t)mol * HIDDEN + t] = sum * inv;

        __syncthreads();   // protect s_part reuse next iteration
    }
}

extern "C" void kernel_launch(void* const* d_in, const int* in_sizes, int n_in,
                              void* d_out, int out_size) {
    const float* atom_hiddens = (const float*)d_in[0];
    const int*   segment_ids  = (const int*)d_in[1];
    float* out = (float*)d_out;

    const int n_atoms = in_sizes[1];          // segment_ids element count
    const int n_mols  = out_size / HIDDEN;    // output rows

    const int gridA = (n_atoms / 4 + 255) / 256 + 1;
    seg_offsets_kernel<<<gridA, 256>>>(segment_ids, n_atoms, n_mols);

    const int gridB = (n_mols < GRID_B) ? n_mols : GRID_B;
    seg_mean_kernel<<<gridB, 128>>>(atom_hiddens, out, n_mols);
}

// round 6
// speedup vs baseline: 1.1303x; 1.0494x over previous
#include <cuda_runtime.h>
#include <cstdint>

// Segment-mean over sorted segment ids, two-phase:
//   A) int4-vectorized boundary scan builds seg_start[] offsets table
//   B) TWO molecules per CTA: all loads issued before one barrier,
//      smem reduce, two coalesced row stores. Amortizes the dependent
//      offset-load prologue over 2x the streamed bytes vs one-mol-per-CTA.
// atom_hiddens: [n_atoms, 128] f32 ; segment_ids: [n_atoms] i32 (sorted) ;
// out: [n_mols, 128] f32.

static constexpr int HIDDEN = 128;
static constexpr int MAX_MOLS = 4 * 1024 * 1024;   // scratch capacity (16 MB)

__device__ int g_seg_start[MAX_MOLS + 1];

// ---- Kernel A: find segment boundaries (int4-vectorized pass over ids) ----
__global__ __launch_bounds__(256)
void seg_offsets_kernel(const int* __restrict__ ids, int n_atoms, int n_mols) {
    const int base = (blockIdx.x * 256 + threadIdx.x) * 4;
    if (base >= n_atoms) return;

    if (base == 0) {
        g_seg_start[__ldg(ids)] = 0;       // first segment start
        g_seg_start[n_mols] = n_atoms;     // sentinel
    }

    if (base + 3 < n_atoms) {
        const int4 v = __ldg(reinterpret_cast<const int4*>(ids + base));
        if (base > 0 && v.x != __ldg(ids + base - 1)) g_seg_start[v.x] = base;
        if (v.y != v.x) g_seg_start[v.y] = base + 1;
        if (v.z != v.y) g_seg_start[v.z] = base + 2;
        if (v.w != v.z) g_seg_start[v.w] = base + 3;
    } else {
        for (int i = base; i < n_atoms; ++i) {
            if (i > 0 && __ldg(ids + i) != __ldg(ids + i - 1))
                g_seg_start[__ldg(ids + i)] = i;
        }
    }
}

// ---- Kernel B: two molecules per CTA, single barrier ----
__global__ __launch_bounds__(128)
void seg_mean_kernel(const float* __restrict__ x,
                     float*       __restrict__ out,
                     int n_mols) {
    const int t    = threadIdx.x;
    const int warp = t >> 5;
    const int lane = t & 31;
    const int mol0 = blockIdx.x * 2;

    __shared__ alignas(16) float s_part[2][4][HIDDEN];

    // Offsets for both molecules: 3 contiguous ints (one cache line,
    // shared with neighbor CTAs).
    const int  s0   = __ldg(&g_seg_start[mol0]);
    const int  e0   = __ldg(&g_seg_start[mol0 + 1]);
    const bool has1 = (mol0 + 1) < n_mols;
    const int  e1   = has1 ? __ldg(&g_seg_start[mol0 + 2]) : e0;

    const float4* __restrict__ xv = reinterpret_cast<const float4*>(x) + lane;

    // Warp w covers rows start+w, start+w+4, ... for each molecule.
    float4 a0 = make_float4(0.f, 0.f, 0.f, 0.f);
    float4 a1 = make_float4(0.f, 0.f, 0.f, 0.f);

    #pragma unroll 5
    for (int r = s0 + warp; r < e0; r += 4) {
        const float4 v = __ldg(xv + (size_t)r * 32);
        a0.x += v.x; a0.y += v.y; a0.z += v.z; a0.w += v.w;
    }
    #pragma unroll 5
    for (int r = e0 + warp; r < e1; r += 4) {
        const float4 v = __ldg(xv + (size_t)r * 32);
        a1.x += v.x; a1.y += v.y; a1.z += v.z; a1.w += v.w;
    }

    *reinterpret_cast<float4*>(&s_part[0][warp][lane * 4]) = a0;
    *reinterpret_cast<float4*>(&s_part[1][warp][lane * 4]) = a1;
    __syncthreads();

    // Epilogue mol0
    {
        const int count = e0 - s0;
        const float inv = (count > 0) ? (1.0f / (float)count) : 0.0f;
        const float sum = s_part[0][0][t] + s_part[0][1][t]
                        + s_part[0][2][t] + s_part[0][3][t];
        out[(size_t)mol0 * HIDDEN + t] = sum * inv;
    }
    // Epilogue mol1
    if (has1) {
        const int count = e1 - e0;
        const float inv = (count > 0) ? (1.0f / (float)count) : 0.0f;
        const float sum = s_part[1][0][t] + s_part[1][1][t]
                        + s_part[1][2][t] + s_part[1][3][t];
        out[(size_t)(mol0 + 1) * HIDDEN + t] = sum * inv;
    }
}

extern "C" void kernel_launch(void* const* d_in, const int* in_sizes, int n_in,
                              void* d_out, int out_size) {
    const float* atom_hiddens = (const float*)d_in[0];
    const int*   segment_ids  = (const int*)d_in[1];
    float* out = (float*)d_out;

    const int n_atoms = in_sizes[1];          // segment_ids element count
    const int n_mols  = out_size / HIDDEN;    // output rows

    const int gridA = (n_atoms / 4 + 255) / 256 + 1;
    seg_offsets_kernel<<<gridA, 256>>>(segment_ids, n_atoms, n_mols);

    const int gridB = (n_mols + 1) / 2;
    seg_mean_kernel<<<gridB, 128>>>(atom_hiddens, out, n_mols);
}

// round 7
// speedup vs baseline: 1.1582x; 1.0247x over previous
#include <cuda_runtime.h>
#include <cstdint>

// Segment-mean over sorted segment ids, two-phase:
//   A) int4-vectorized boundary scan builds seg_start[] offsets table
//   B) TWO molecules per CTA, single barrier; streaming cache hints:
//      __ldcs on the once-read feature stream, __stcs on the output.
// atom_hiddens: [n_atoms, 128] f32 ; segment_ids: [n_atoms] i32 (sorted) ;
// out: [n_mols, 128] f32.

static constexpr int HIDDEN = 128;
static constexpr int MAX_MOLS = 4 * 1024 * 1024;   // scratch capacity (16 MB)

__device__ int g_seg_start[MAX_MOLS + 1];

// ---- Kernel A: find segment boundaries (int4-vectorized pass over ids) ----
__global__ __launch_bounds__(256)
void seg_offsets_kernel(const int* __restrict__ ids, int n_atoms, int n_mols) {
    const int base = (blockIdx.x * 256 + threadIdx.x) * 4;
    if (base >= n_atoms) return;

    if (base == 0) {
        g_seg_start[__ldg(ids)] = 0;       // first segment start
        g_seg_start[n_mols] = n_atoms;     // sentinel
    }

    if (base + 3 < n_atoms) {
        const int4 v = __ldg(reinterpret_cast<const int4*>(ids + base));
        if (base > 0 && v.x != __ldg(ids + base - 1)) g_seg_start[v.x] = base;
        if (v.y != v.x) g_seg_start[v.y] = base + 1;
        if (v.z != v.y) g_seg_start[v.z] = base + 2;
        if (v.w != v.z) g_seg_start[v.w] = base + 3;
    } else {
        for (int i = base; i < n_atoms; ++i) {
            if (i > 0 && __ldg(ids + i) != __ldg(ids + i - 1))
                g_seg_start[__ldg(ids + i)] = i;
        }
    }
}

// ---- Kernel B: two molecules per CTA, single barrier, streaming hints ----
__global__ __launch_bounds__(128)
void seg_mean_kernel(const float* __restrict__ x,
                     float*       __restrict__ out,
                     int n_mols) {
    const int t    = threadIdx.x;
    const int warp = t >> 5;
    const int lane = t & 31;
    const int mol0 = blockIdx.x * 2;

    __shared__ alignas(16) float s_part[2][4][HIDDEN];

    // Offsets for both molecules: 3 contiguous ints (one cache line,
    // shared with neighbor CTAs) -- keep these cached (__ldg).
    const int  s0   = __ldg(&g_seg_start[mol0]);
    const int  e0   = __ldg(&g_seg_start[mol0 + 1]);
    const bool has1 = (mol0 + 1) < n_mols;
    const int  e1   = has1 ? __ldg(&g_seg_start[mol0 + 2]) : e0;

    const float4* __restrict__ xv = reinterpret_cast<const float4*>(x) + lane;

    // Warp w covers rows start+w, start+w+4, ... for each molecule.
    // __ldcs: evict-first streaming loads -- this data is read exactly once.
    float4 a0 = make_float4(0.f, 0.f, 0.f, 0.f);
    float4 a1 = make_float4(0.f, 0.f, 0.f, 0.f);

    #pragma unroll 5
    for (int r = s0 + warp; r < e0; r += 4) {
        const float4 v = __ldcs(xv + (size_t)r * 32);
        a0.x += v.x; a0.y += v.y; a0.z += v.z; a0.w += v.w;
    }
    #pragma unroll 5
    for (int r = e0 + warp; r < e1; r += 4) {
        const float4 v = __ldcs(xv + (size_t)r * 32);
        a1.x += v.x; a1.y += v.y; a1.z += v.z; a1.w += v.w;
    }

    *reinterpret_cast<float4*>(&s_part[0][warp][lane * 4]) = a0;
    *reinterpret_cast<float4*>(&s_part[1][warp][lane * 4]) = a1;
    __syncthreads();

    // Epilogue mol0 (streaming store, no write-allocate pollution)
    {
        const int count = e0 - s0;
        const float inv = (count > 0) ? (1.0f / (float)count) : 0.0f;
        const float sum = s_part[0][0][t] + s_part[0][1][t]
                        + s_part[0][2][t] + s_part[0][3][t];
        __stcs(out + (size_t)mol0 * HIDDEN + t, sum * inv);
    }
    // Epilogue mol1
    if (has1) {
        const int count = e1 - e0;
        const float inv = (count > 0) ? (1.0f / (float)count) : 0.0f;
        const float sum = s_part[1][0][t] + s_part[1][1][t]
                        + s_part[1][2][t] + s_part[1][3][t];
        __stcs(out + (size_t)(mol0 + 1) * HIDDEN + t, sum * inv);
    }
}

extern "C" void kernel_launch(void* const* d_in, const int* in_sizes, int n_in,
                              void* d_out, int out_size) {
    const float* atom_hiddens = (const float*)d_in[0];
    const int*   segment_ids  = (const int*)d_in[1];
    float* out = (float*)d_out;

    const int n_atoms = in_sizes[1];          // segment_ids element count
    const int n_mols  = out_size / HIDDEN;    // output rows

    const int gridA = (n_atoms / 4 + 255) / 256 + 1;
    seg_offsets_kernel<<<gridA, 256>>>(segment_ids, n_atoms, n_mols);

    const int gridB = (n_mols + 1) / 2;
    seg_mean_kernel<<<gridB, 128>>>(atom_hiddens, out, n_mols);
}

// round 8
// speedup vs baseline: 1.1632x; 1.0044x over previous
#include <cuda_runtime.h>
#include <cstdint>

// Segment-mean over sorted segment ids, two-phase with PDL overlap:
//   A) int4-vectorized boundary scan builds seg_start[]; signals dependents
//      early via griddepcontrol.launch_dependents.
//   B) TWO molecules per CTA (proven optimal shape, ~LTS-ceiling-bound);
//      launched with programmatic stream serialization, waits on A only
//      right before consuming the offsets.
// atom_hiddens: [n_atoms, 128] f32 ; segment_ids: [n_atoms] i32 (sorted) ;
// out: [n_mols, 128] f32.

static constexpr int HIDDEN = 128;
static constexpr int MAX_MOLS = 4 * 1024 * 1024;   // scratch capacity (16 MB)

__device__ int g_seg_start[MAX_MOLS + 1];

// ---- Kernel A: find segment boundaries (int4-vectorized pass over ids) ----
__global__ __launch_bounds__(256)
void seg_offsets_kernel(const int* __restrict__ ids, int n_atoms, int n_mols) {
    const int base = (blockIdx.x * 256 + threadIdx.x) * 4;

    if (base < n_atoms) {
        if (base == 0) {
            g_seg_start[__ldg(ids)] = 0;       // first segment start
            g_seg_start[n_mols] = n_atoms;     // sentinel
        }

        if (base + 3 < n_atoms) {
            const int4 v = __ldg(reinterpret_cast<const int4*>(ids + base));
            if (base > 0 && v.x != __ldg(ids + base - 1)) g_seg_start[v.x] = base;
            if (v.y != v.x) g_seg_start[v.y] = base + 1;
            if (v.z != v.y) g_seg_start[v.z] = base + 2;
            if (v.w != v.z) g_seg_start[v.w] = base + 3;
        } else {
            for (int i = base; i < n_atoms; ++i) {
                if (i > 0 && __ldg(ids + i) != __ldg(ids + i - 1))
                    g_seg_start[__ldg(ids + i)] = i;
            }
        }
    }

    // All boundary stores above are visible to the dependent grid after this.
    asm volatile("griddepcontrol.launch_dependents;");
}

// ---- Kernel B: two molecules per CTA, single barrier, streaming hints ----
__global__ __launch_bounds__(128)
void seg_mean_kernel(const float* __restrict__ x,
                     float*       __restrict__ out,
                     int n_mols) {
    const int t    = threadIdx.x;
    const int warp = t >> 5;
    const int lane = t & 31;
    const int mol0 = blockIdx.x * 2;

    __shared__ alignas(16) float s_part[2][4][HIDDEN];

    // Block until kernel A's boundary writes are visible (PDL handshake).
    asm volatile("griddepcontrol.wait;" ::: "memory");

    // Offsets for both molecules: 3 contiguous ints (one cache line,
    // shared with neighbor CTAs) -- keep these cached (__ldg).
    const int  s0   = __ldg(&g_seg_start[mol0]);
    const int  e0   = __ldg(&g_seg_start[mol0 + 1]);
    const bool has1 = (mol0 + 1) < n_mols;
    const int  e1   = has1 ? __ldg(&g_seg_start[mol0 + 2]) : e0;

    const float4* __restrict__ xv = reinterpret_cast<const float4*>(x) + lane;

    // Warp w covers rows start+w, start+w+4, ... for each molecule.
    // __ldcs: evict-first streaming loads -- this data is read exactly once.
    float4 a0 = make_float4(0.f, 0.f, 0.f, 0.f);
    float4 a1 = make_float4(0.f, 0.f, 0.f, 0.f);

    #pragma unroll 5
    for (int r = s0 + warp; r < e0; r += 4) {
        const float4 v = __ldcs(xv + (size_t)r * 32);
        a0.x += v.x; a0.y += v.y; a0.z += v.z; a0.w += v.w;
    }
    #pragma unroll 5
    for (int r = e0 + warp; r < e1; r += 4) {
        const float4 v = __ldcs(xv + (size_t)r * 32);
        a1.x += v.x; a1.y += v.y; a1.z += v.z; a1.w += v.w;
    }

    *reinterpret_cast<float4*>(&s_part[0][warp][lane * 4]) = a0;
    *reinterpret_cast<float4*>(&s_part[1][warp][lane * 4]) = a1;
    __syncthreads();

    // Epilogue mol0 (streaming store, no write-allocate pollution)
    {
        const int count = e0 - s0;
        const float inv = (count > 0) ? (1.0f / (float)count) : 0.0f;
        const float sum = s_part[0][0][t] + s_part[0][1][t]
                        + s_part[0][2][t] + s_part[0][3][t];
        __stcs(out + (size_t)mol0 * HIDDEN + t, sum * inv);
    }
    // Epilogue mol1
    if (has1) {
        const int count = e1 - e0;
        const float inv = (count > 0) ? (1.0f / (float)count) : 0.0f;
        const float sum = s_part[1][0][t] + s_part[1][1][t]
                        + s_part[1][2][t] + s_part[1][3][t];
        __stcs(out + (size_t)(mol0 + 1) * HIDDEN + t, sum * inv);
    }
}

extern "C" void kernel_launch(void* const* d_in, const int* in_sizes, int n_in,
                              void* d_out, int out_size) {
    const float* atom_hiddens = (const float*)d_in[0];
    const int*   segment_ids  = (const int*)d_in[1];
    float* out = (float*)d_out;

    const int n_atoms = in_sizes[1];          // segment_ids element count
    const int n_mols  = out_size / HIDDEN;    // output rows

    const int gridA = (n_atoms / 4 + 255) / 256 + 1;
    seg_offsets_kernel<<<gridA, 256>>>(segment_ids, n_atoms, n_mols);

    // Kernel B with programmatic dependent launch: overlaps its launch and
    // prologue with kernel A; the griddepcontrol.wait inside orders the
    // offset reads after A's stores.
    const int gridB = (n_mols + 1) / 2;

    cudaLaunchConfig_t cfg = {};
    cfg.gridDim  = dim3((unsigned)gridB, 1, 1);
    cfg.blockDim = dim3(128, 1, 1);
    cfg.dynamicSmemBytes = 0;
    cfg.stream = 0;

    cudaLaunchAttribute attrs[1];
    attrs[0].id = cudaLaunchAttributeProgrammaticStreamSerialization;
    attrs[0].val.programmaticStreamSerializationAllowed = 1;
    cfg.attrs = attrs;
    cfg.numAttrs = 1;

    cudaError_t err = cudaLaunchKernelEx(&cfg, seg_mean_kernel,
                                         atom_hiddens, out, n_mols);
    if (err != cudaSuccess) {
        // Fallback: plain launch (griddepcontrol.wait is a no-op without PDL).
        seg_mean_kernel<<<gridB, 128>>>(atom_hiddens, out, n_mols);
    }
}